// round 11
// baseline (speedup 1.0000x reference)
#include <cuda_runtime.h>
#include <cstdint>

#define B_    2048
#define N_    32
#define F_    64
#define E_    8
#define H_    128
#define NA_   4
#define NACT_ 16
#define KTOT  585      // 512 agg + 64 root + 8 mask-bias + 1 const-bias
#define KK_   76       // k8 blocks (K padded to 608)
#define KPAD  608
#define ASTR  72       // A smem row stride in floats; 72%32==8 -> conflict-free frags
#define NCHUNK 19      // 19 chunks x 4 k8-blocks

// __device__ scratch (no allocations allowed)
__device__ float g_Wcat[KTOT * H_];            // logical [k][h]
__device__ uint4 g_Bpack[KK_ * 4 * 2 * 32];    // [kk][ng][half][t] fragment-packed tf32
__device__ uint4 g_W1pack[NA_ * 16 * 4 * 2 * 32];  // [a][kk][ng][half][t]
__device__ float g_pooled[B_ * H_];            // [b][h]

static __device__ __forceinline__ uint32_t f2tf32(float f) {
    uint32_t r; asm("cvt.rna.tf32.f32 %0, %1;" : "=r"(r) : "f"(f)); return r;
}
static __device__ __forceinline__ void mma_tf32(float c[4], const uint32_t a[4],
                                                uint32_t b0, uint32_t b1) {
    asm volatile(
        "mma.sync.aligned.m16n8k8.row.col.f32.tf32.tf32.f32 "
        "{%0,%1,%2,%3},{%4,%5,%6,%7},{%8,%9},{%0,%1,%2,%3};"
        : "+f"(c[0]), "+f"(c[1]), "+f"(c[2]), "+f"(c[3])
        : "r"(a[0]), "r"(a[1]), "r"(a[2]), "r"(a[3]), "r"(b0), "r"(b1));
}

// ---------------------------------------------------------------------------
// Kernel A: fold We/be into Wrel/Wroot/brel -> g_Wcat[585][128]
// ---------------------------------------------------------------------------
__global__ void precompute_wcat(const float* __restrict__ We,
                                const float* __restrict__ be,
                                const float* __restrict__ Wrel,
                                const float* __restrict__ Wroot,
                                const float* __restrict__ brel) {
    __shared__ float vec[H_];
    const int r = blockIdx.x;
    const int h = threadIdx.x;
    const float* Bmat;
    float addv = 0.0f;
    if (r < 512) {
        int e = r >> 6, d = r & 63;
        vec[h] = We[d * H_ + h];
        Bmat = Wrel + e * H_ * H_;
    } else if (r < 576) {
        int d = r - 512;
        vec[h] = We[d * H_ + h];
        Bmat = Wroot;
    } else if (r < 584) {
        int e = r - 576;
        vec[h] = be[h];
        Bmat = Wrel + e * H_ * H_;
    } else {
        vec[h] = be[h];
        Bmat = Wroot;
        addv = brel[h];
    }
    __syncthreads();
    float a0 = 0.f, a1 = 0.f, a2 = 0.f, a3 = 0.f;
    #pragma unroll 8
    for (int t = 0; t < H_; t += 4) {
        a0 = fmaf(vec[t],     __ldg(Bmat + (t    ) * H_ + h), a0);
        a1 = fmaf(vec[t + 1], __ldg(Bmat + (t + 1) * H_ + h), a1);
        a2 = fmaf(vec[t + 2], __ldg(Bmat + (t + 2) * H_ + h), a2);
        a3 = fmaf(vec[t + 3], __ldg(Bmat + (t + 3) * H_ + h), a3);
    }
    g_Wcat[r * H_ + h] = addv + ((a0 + a1) + (a2 + a3));
}

// ---------------------------------------------------------------------------
// Kernel A2: repack g_Wcat into mma B-fragment order (tf32), zero-pad k>=585.
// ---------------------------------------------------------------------------
__global__ void repack_b() {
    int kk   = blockIdx.x;
    int t    = threadIdx.x & 31;
    int half = (threadIdx.x >> 5) & 1;
    int ng   = threadIdx.x >> 6;
    int k0 = kk * 8 + (t & 3);
    int k1 = k0 + 4;
    int c0 = ng * 32 + (half * 2 + 0) * 8 + (t >> 2);
    int c1 = ng * 32 + (half * 2 + 1) * 8 + (t >> 2);
    float v0 = (k0 < KTOT) ? g_Wcat[k0 * H_ + c0] : 0.f;
    float v1 = (k1 < KTOT) ? g_Wcat[k1 * H_ + c0] : 0.f;
    float v2 = (k0 < KTOT) ? g_Wcat[k0 * H_ + c1] : 0.f;
    float v3 = (k1 < KTOT) ? g_Wcat[k1 * H_ + c1] : 0.f;
    g_Bpack[((kk * 4 + ng) * 2 + half) * 32 + t] =
        make_uint4(f2tf32(v0), f2tf32(v1), f2tf32(v2), f2tf32(v3));
}

// ---------------------------------------------------------------------------
// Kernel A3: repack W1 into mma B-fragment order (tf32). K=128 = 16 k8, exact.
// grid = NA_*16 (a = bx>>4, kk = bx&15), block 256.
// ---------------------------------------------------------------------------
__global__ void repack_w1(const float* __restrict__ W1) {
    int a    = blockIdx.x >> 4;
    int kk   = blockIdx.x & 15;
    int t    = threadIdx.x & 31;
    int half = (threadIdx.x >> 5) & 1;
    int ng   = threadIdx.x >> 6;
    int k0 = kk * 8 + (t & 3);
    int k1 = k0 + 4;
    int c0 = ng * 32 + (half * 2 + 0) * 8 + (t >> 2);
    int c1 = ng * 32 + (half * 2 + 1) * 8 + (t >> 2);
    const float* Wp = W1 + (size_t)a * H_ * H_;
    g_W1pack[(((a * 16 + kk) * 4 + ng) * 2 + half) * 32 + t] =
        make_uint4(f2tf32(Wp[k0 * H_ + c0]), f2tf32(Wp[k1 * H_ + c0]),
                   f2tf32(Wp[k0 * H_ + c1]), f2tf32(Wp[k1 * H_ + c1]));
}

// ---------------------------------------------------------------------------
// Kernel B: main kernel (byte-identical to passing R10 version).
// ---------------------------------------------------------------------------
struct SmemM {
    union AB {
        float A[KPAD][ASTR];         // 175104 B, k-major: A[k][m], m = q*32+j
        float Cpart[4][64][132];     // 135168 B: k-split partials (epilogue)
    } ab;
    unsigned masks[512];             // [q*256 + e*32 + j], bit i = A[b,e,i,j]
    float    cinv[512];
};

__global__ __launch_bounds__(512, 1) void critic_main(
    const float* __restrict__ unary,    // [B,N,F]
    const int*   __restrict__ binary)   // [B,N,N,E]
{
    extern __shared__ char raw[];
    SmemM& s = *reinterpret_cast<SmemM*>(raw);

    const int tid  = threadIdx.x;
    const int lane = tid & 31;
    const int w    = tid >> 5;          // 16 warps
    const int bg0  = blockIdx.x * 2;    // first batch of this CTA

    // ---- u -> A root rows (pre-rounded tf32): A[512+d][q*32+j] = u[q][j][d] ----
    {
        const float* up = unary + (size_t)bg0 * (N_ * F_);
        #pragma unroll
        for (int p = 0; p < 8; ++p) {
            int li = tid + p * 512;            // 4096 elements
            int q  = li >> 11;
            int j  = (li >> 6) & 31;
            int d  = li & 63;
            s.ab.A[512 + d][q * 32 + j] = __uint_as_float(f2tf32(up[li]));
        }
    }
    s.masks[tid] = 0u;
    __syncthreads();

    // ---- binary -> bitmasks: register-accumulate then 8 atomicOr ----
    {
        const int4* bb = reinterpret_cast<const int4*>(binary + (size_t)bg0 * (N_ * N_ * E_));
        const int j  = (tid >> 1) & 31;
        const int e0 = (tid & 1) * 4;
        const int ib = tid >> 6;
        unsigned acc[2][4];
        #pragma unroll
        for (int q = 0; q < 2; ++q)
            #pragma unroll
            for (int sl = 0; sl < 4; ++sl) acc[q][sl] = 0u;
        #pragma unroll
        for (int p = 0; p < 8; ++p) {
            int4 v = bb[tid + p * 512];
            int q = p >> 2;
            unsigned bit = 1u << ((ib + 8 * (p & 3)) & 31);
            if (v.x) acc[q][0] |= bit;
            if (v.y) acc[q][1] |= bit;
            if (v.z) acc[q][2] |= bit;
            if (v.w) acc[q][3] |= bit;
        }
        #pragma unroll
        for (int q = 0; q < 2; ++q)
            #pragma unroll
            for (int sl = 0; sl < 4; ++sl)
                atomicOr(&s.masks[q * 256 + (e0 + sl) * 32 + j], acc[q][sl]);
    }
    __syncthreads();

    { int d = __popc(s.masks[tid]); s.cinv[tid] = d ? (1.0f / (float)d) : 0.0f; }
    __syncthreads();

    // ---- tensor-core aggregation ----
    {
        const int gr = lane >> 2, gc = lane & 3;
        const int q  = w >> 3;
        const int mt = (w >> 2) & 1;
        const int np = w & 3;

        uint32_t uf[2][4][2];     // [nt2][kb][b0/b1]
        #pragma unroll
        for (int nt2 = 0; nt2 < 2; ++nt2) {
            int nt = np * 2 + nt2;
            #pragma unroll
            for (int kb = 0; kb < 4; ++kb) {
                uf[nt2][kb][0] = __float_as_uint(s.ab.A[512 + nt * 8 + gr][q * 32 + kb * 8 + gc]);
                uf[nt2][kb][1] = __float_as_uint(s.ab.A[512 + nt * 8 + gr][q * 32 + kb * 8 + gc + 4]);
            }
        }
        const int mcol = q * 32 + mt * 16 + gr;
        #pragma unroll
        for (int e = 0; e < E_; ++e) {
            const int mb = q * 256 + e * 32 + mt * 16 + gr;
            unsigned mr0 = s.masks[mb];
            unsigned mr1 = s.masks[mb + 8];
            float ci0 = s.cinv[mb];
            float ci1 = s.cinv[mb + 8];
            float acc0[4] = {0.f, 0.f, 0.f, 0.f};
            float acc1[4] = {0.f, 0.f, 0.f, 0.f};
            #pragma unroll
            for (int kb = 0; kb < 4; ++kb) {
                int bi = kb * 8 + gc;
                uint32_t ar[4];
                ar[0] = ((mr0 >> bi) & 1u)       ? 0x3f800000u : 0u;
                ar[1] = ((mr1 >> bi) & 1u)       ? 0x3f800000u : 0u;
                ar[2] = ((mr0 >> (bi + 4)) & 1u) ? 0x3f800000u : 0u;
                ar[3] = ((mr1 >> (bi + 4)) & 1u) ? 0x3f800000u : 0u;
                mma_tf32(acc0, ar, uf[0][kb][0], uf[0][kb][1]);
                mma_tf32(acc1, ar, uf[1][kb][0], uf[1][kb][1]);
            }
            {
                int row = e * 64 + (np * 2 + 0) * 8 + 2 * gc;
                s.ab.A[row][mcol]         = __uint_as_float(f2tf32(acc0[0] * ci0));
                s.ab.A[row + 1][mcol]     = __uint_as_float(f2tf32(acc0[1] * ci0));
                s.ab.A[row][mcol + 8]     = __uint_as_float(f2tf32(acc0[2] * ci1));
                s.ab.A[row + 1][mcol + 8] = __uint_as_float(f2tf32(acc0[3] * ci1));
            }
            {
                int row = e * 64 + (np * 2 + 1) * 8 + 2 * gc;
                s.ab.A[row][mcol]         = __uint_as_float(f2tf32(acc1[0] * ci0));
                s.ab.A[row + 1][mcol]     = __uint_as_float(f2tf32(acc1[1] * ci0));
                s.ab.A[row][mcol + 8]     = __uint_as_float(f2tf32(acc1[2] * ci1));
                s.ab.A[row + 1][mcol + 8] = __uint_as_float(f2tf32(acc1[3] * ci1));
            }
        }
    }
    // special k-rows (exact in tf32): 576..583 deg>0, 584 ones, 585..607 zeros
    {
        int q2 = tid >> 8, e2 = (tid >> 5) & 7, j2 = tid & 31;
        s.ab.A[576 + e2][q2 * 32 + j2] = s.masks[tid] ? 1.0f : 0.0f;
        if (tid < 64) s.ab.A[584][tid] = 1.0f;
        for (int r = tid; r < 23 * 64; r += 512)
            s.ab.A[585 + (r >> 6)][r & 63] = 0.0f;
    }
    __syncthreads();   // A fully ready; no more barriers until epilogue

    // ---- main GEMM: B direct from L2 (__ldg), depth-1 prefetch, no barriers ----
    const int mw2 = w & 1;
    const int ngp = (w >> 1) & 1;
    const int ks  = w >> 2;
    const int fc  = lane & 3;
    const int fr  = lane >> 2;
    const int m0  = mw2 * 32;

    float acc[2][8][4];
    #pragma unroll
    for (int mt2 = 0; mt2 < 2; ++mt2)
        #pragma unroll
        for (int nn = 0; nn < 8; ++nn)
            #pragma unroll
            for (int i = 0; i < 4; ++i) acc[mt2][nn][i] = 0.0f;

    const uint4* bptr = g_Bpack + (size_t)((ks * 4 + ngp * 2) * 64) + lane;
    uint4 nb0 = __ldg(bptr);
    uint4 nb1 = __ldg(bptr + 32);
    uint4 nb2 = __ldg(bptr + 64);
    uint4 nb3 = __ldg(bptr + 96);

    for (int ch = 0; ch < NCHUNK; ++ch) {
        const int k0 = (ch * 4 + ks) * 8;
        uint32_t a0[4], a1[4];
        a0[0] = __float_as_uint(s.ab.A[k0 + fc][m0 + fr]);
        a0[1] = __float_as_uint(s.ab.A[k0 + fc][m0 + fr + 8]);
        a0[2] = __float_as_uint(s.ab.A[k0 + fc + 4][m0 + fr]);
        a0[3] = __float_as_uint(s.ab.A[k0 + fc + 4][m0 + fr + 8]);
        a1[0] = __float_as_uint(s.ab.A[k0 + fc][m0 + 16 + fr]);
        a1[1] = __float_as_uint(s.ab.A[k0 + fc][m0 + 16 + fr + 8]);
        a1[2] = __float_as_uint(s.ab.A[k0 + fc + 4][m0 + 16 + fr]);
        a1[3] = __float_as_uint(s.ab.A[k0 + fc + 4][m0 + 16 + fr + 8]);

        uint4 cb0 = nb0, cb1 = nb1, cb2 = nb2, cb3 = nb3;
        if (ch + 1 < NCHUNK) {
            bptr += 1024;
            nb0 = __ldg(bptr);
            nb1 = __ldg(bptr + 32);
            nb2 = __ldg(bptr + 64);
            nb3 = __ldg(bptr + 96);
        }

        mma_tf32(acc[0][0], a0, cb0.x, cb0.y);
        mma_tf32(acc[0][1], a0, cb0.z, cb0.w);
        mma_tf32(acc[0][2], a0, cb1.x, cb1.y);
        mma_tf32(acc[0][3], a0, cb1.z, cb1.w);
        mma_tf32(acc[0][4], a0, cb2.x, cb2.y);
        mma_tf32(acc[0][5], a0, cb2.z, cb2.w);
        mma_tf32(acc[0][6], a0, cb3.x, cb3.y);
        mma_tf32(acc[0][7], a0, cb3.z, cb3.w);
        mma_tf32(acc[1][0], a1, cb0.x, cb0.y);
        mma_tf32(acc[1][1], a1, cb0.z, cb0.w);
        mma_tf32(acc[1][2], a1, cb1.x, cb1.y);
        mma_tf32(acc[1][3], a1, cb1.z, cb1.w);
        mma_tf32(acc[1][4], a1, cb2.x, cb2.y);
        mma_tf32(acc[1][5], a1, cb2.z, cb2.w);
        mma_tf32(acc[1][6], a1, cb3.x, cb3.y);
        mma_tf32(acc[1][7], a1, cb3.z, cb3.w);
    }

    __syncthreads();
    {
        float* Cp = &s.ab.Cpart[ks][0][0];
        #pragma unroll
        for (int mt2 = 0; mt2 < 2; ++mt2) {
            const int row = m0 + mt2 * 16 + fr;
            #pragma unroll
            for (int nn = 0; nn < 8; ++nn) {
                const int col = ngp * 64 + nn * 8 + 2 * fc;
                Cp[row * 132 + col]           = acc[mt2][nn][0];
                Cp[row * 132 + col + 1]       = acc[mt2][nn][1];
                Cp[(row + 8) * 132 + col]     = acc[mt2][nn][2];
                Cp[(row + 8) * 132 + col + 1] = acc[mt2][nn][3];
            }
        }
    }
    __syncthreads();

    if (tid < 256) {
        const int q = tid >> 7, h = tid & 127;
        float mx = -3.0e38f;
        #pragma unroll 4
        for (int j = 0; j < N_; ++j) {
            const int row = q * 32 + j;
            float v = s.ab.Cpart[0][row][h] + s.ab.Cpart[1][row][h]
                    + s.ab.Cpart[2][row][h] + s.ab.Cpart[3][row][h];
            mx = fmaxf(mx, v);
        }
        g_pooled[(size_t)(bg0 + q) * H_ + h] = fmaxf(mx, 0.0f);
    }
}

// ---------------------------------------------------------------------------
// Kernel C: heads via tf32 mma. grid = 4 agents x 32 tiles of 64 batches
// (128 CTAs, 1 wave), 256 threads (8 warps). Warp tile m32 x n32 x k128,
// no k-split, B (W1 fragments) direct from L2 with depth-1 prefetch.
// ---------------------------------------------------------------------------
struct SmemH {
    union AZ {
        float Ah[H_][ASTR];       // 36864 B: pooled transposed [k=h_in][m=batch]
        float Z[64][132];         // 33792 B: z (epilogue)
    } az;
    int cols[64];
};

__global__ __launch_bounds__(256, 2) void heads_kernel(
    const float* __restrict__ actions,  // [NA,B,NACT]
    const float* __restrict__ b1,       // [NA,H]
    const float* __restrict__ W2,       // [NA,H,NACT]
    const float* __restrict__ b2,       // [NA,NACT]
    float* __restrict__ qout)           // [NA,B,1]
{
    extern __shared__ char raw[];
    SmemH& s = *reinterpret_cast<SmemH*>(raw);
    const int tid  = threadIdx.x;
    const int lane = tid & 31;
    const int w    = tid >> 5;          // 8 warps
    const int a    = blockIdx.x >> 5;
    const int b0   = (blockIdx.x & 31) * 64;

    // ---- stage pooled tile transposed + tf32-rounded: Ah[h][m] ----
    {
        const float4* ps = reinterpret_cast<const float4*>(g_pooled + (size_t)b0 * H_);
        #pragma unroll
        for (int p = 0; p < 8; ++p) {
            int idx = tid + p * 256;          // 2048 float4s
            float4 v = ps[idx];
            int m  = idx >> 5;                // batch 0..63
            int h4 = (idx & 31) * 4;
            s.az.Ah[h4 + 0][m] = __uint_as_float(f2tf32(v.x));
            s.az.Ah[h4 + 1][m] = __uint_as_float(f2tf32(v.y));
            s.az.Ah[h4 + 2][m] = __uint_as_float(f2tf32(v.z));
            s.az.Ah[h4 + 3][m] = __uint_as_float(f2tf32(v.w));
        }
    }
    if (tid < 64) {
        const float* ap = actions + ((size_t)a * B_ + b0 + tid) * NACT_;
        float best = ap[0]; int col = 0;
        #pragma unroll
        for (int k = 1; k < NACT_; ++k) {
            float v = ap[k];
            if (v > best) { best = v; col = k; }
        }
        s.cols[tid] = col;
    }
    __syncthreads();

    // ---- z GEMM: warp = (mw2 = w&1: m32, ng = w>>1: n32). 16 k8, 8 mma each.
    const int mw2 = w & 1;
    const int ng  = w >> 1;
    const int fc  = lane & 3;
    const int fr  = lane >> 2;
    const int m0  = mw2 * 32;

    float acc[2][4][4];
    #pragma unroll
    for (int mt2 = 0; mt2 < 2; ++mt2)
        #pragma unroll
        for (int nn = 0; nn < 4; ++nn)
            #pragma unroll
            for (int i = 0; i < 4; ++i) acc[mt2][nn][i] = 0.0f;

    // W1 fragments: g_W1pack[((a*16 + kk)*4 + ng)*2 + half][lane]; kk stride 256
    const uint4* bptr = g_W1pack + (size_t)((a * 16 * 4 + ng) * 2) * 32 + lane;
    uint4 nb0 = __ldg(bptr);
    uint4 nb1 = __ldg(bptr + 32);

    #pragma unroll 4
    for (int kk = 0; kk < 16; ++kk) {
        const int k0 = kk * 8;
        uint32_t a0[4], a1[4];
        a0[0] = __float_as_uint(s.az.Ah[k0 + fc][m0 + fr]);
        a0[1] = __float_as_uint(s.az.Ah[k0 + fc][m0 + fr + 8]);
        a0[2] = __float_as_uint(s.az.Ah[k0 + fc + 4][m0 + fr]);
        a0[3] = __float_as_uint(s.az.Ah[k0 + fc + 4][m0 + fr + 8]);
        a1[0] = __float_as_uint(s.az.Ah[k0 + fc][m0 + 16 + fr]);
        a1[1] = __float_as_uint(s.az.Ah[k0 + fc][m0 + 16 + fr + 8]);
        a1[2] = __float_as_uint(s.az.Ah[k0 + fc + 4][m0 + 16 + fr]);
        a1[3] = __float_as_uint(s.az.Ah[k0 + fc + 4][m0 + 16 + fr + 8]);

        uint4 cb0 = nb0, cb1 = nb1;
        if (kk + 1 < 16) {
            bptr += 256;
            nb0 = __ldg(bptr);
            nb1 = __ldg(bptr + 32);
        }

        mma_tf32(acc[0][0], a0, cb0.x, cb0.y);
        mma_tf32(acc[0][1], a0, cb0.z, cb0.w);
        mma_tf32(acc[0][2], a0, cb1.x, cb1.y);
        mma_tf32(acc[0][3], a0, cb1.z, cb1.w);
        mma_tf32(acc[1][0], a1, cb0.x, cb0.y);
        mma_tf32(acc[1][1], a1, cb0.z, cb0.w);
        mma_tf32(acc[1][2], a1, cb1.x, cb1.y);
        mma_tf32(acc[1][3], a1, cb1.z, cb1.w);
    }
    __syncthreads();   // all warps done reading Ah; Z overlays it

    // ---- epilogue: +b1, LeakyReLU, store Z ----
    #pragma unroll
    for (int nn = 0; nn < 4; ++nn) {
        const int col = ng * 32 + nn * 8 + 2 * fc;
        float bv0 = __ldg(b1 + a * H_ + col);
        float bv1 = __ldg(b1 + a * H_ + col + 1);
        #pragma unroll
        for (int mt2 = 0; mt2 < 2; ++mt2) {
            const int row = m0 + mt2 * 16 + fr;
            float z00 = acc[mt2][nn][0] + bv0;
            float z01 = acc[mt2][nn][1] + bv1;
            float z10 = acc[mt2][nn][2] + bv0;
            float z11 = acc[mt2][nn][3] + bv1;
            s.az.Z[row][col]         = (z00 > 0.f) ? z00 : 0.01f * z00;
            s.az.Z[row][col + 1]     = (z01 > 0.f) ? z01 : 0.01f * z01;
            s.az.Z[row + 8][col]     = (z10 > 0.f) ? z10 : 0.01f * z10;
            s.az.Z[row + 8][col + 1] = (z11 > 0.f) ? z11 : 0.01f * z11;
        }
    }
    __syncthreads();

    // ---- q = z @ W2[:, col] + b2: thread = (b = tid>>2, qt = tid&3), 32 h ----
    {
        const int b  = tid >> 2;
        const int qt = tid & 3;
        const int col = s.cols[b];
        const float* w2p = W2 + (size_t)a * H_ * NACT_ + col;
        float part = 0.f;
        #pragma unroll 8
        for (int i = 0; i < 32; ++i) {
            int h = i * 4 + qt;
            part = fmaf(s.az.Z[b][h], __ldg(w2p + h * NACT_), part);
        }
        part += __shfl_xor_sync(0xffffffffu, part, 1);
        part += __shfl_xor_sync(0xffffffffu, part, 2);
        if (qt == 0)
            qout[(size_t)a * B_ + b0 + b] = part + b2[a * NACT_ + col];
    }
}

// ---------------------------------------------------------------------------
extern "C" void kernel_launch(void* const* d_in, const int* in_sizes, int n_in,
                              void* d_out, int out_size) {
    const float* unary   = (const float*)d_in[0];
    const int*   binary  = (const int*)  d_in[1];
    const float* actions = (const float*)d_in[2];
    const float* We      = (const float*)d_in[3];
    const float* be      = (const float*)d_in[4];
    const float* Wrel    = (const float*)d_in[5];
    const float* Wroot   = (const float*)d_in[6];
    const float* brel    = (const float*)d_in[7];
    const float* W1      = (const float*)d_in[8];
    const float* b1      = (const float*)d_in[9];
    const float* W2      = (const float*)d_in[10];
    const float* b2      = (const float*)d_in[11];
    float* qout = (float*)d_out;

    cudaFuncSetAttribute(critic_main, cudaFuncAttributeMaxDynamicSharedMemorySize,
                         (int)sizeof(SmemM));
    cudaFuncSetAttribute(heads_kernel, cudaFuncAttributeMaxDynamicSharedMemorySize,
                         (int)sizeof(SmemH));

    precompute_wcat<<<KTOT, H_>>>(We, be, Wrel, Wroot, brel);
    repack_b<<<KK_, 256>>>();
    repack_w1<<<NA_ * 16, 256>>>(W1);
    critic_main<<<B_ / 2, 512, sizeof(SmemM)>>>(unary, binary);
    heads_kernel<<<NA_ * 32, 256, sizeof(SmemH)>>>(actions, b1, W2, b2, qout);
}

// round 13
// speedup vs baseline: 1.0374x; 1.0374x over previous
#include <cuda_runtime.h>
#include <cstdint>

#define B_    2048
#define N_    32
#define F_    64
#define E_    8
#define H_    128
#define NA_   4
#define NACT_ 16
#define KTOT  585      // 512 agg + 64 root + 8 mask-bias + 1 const-bias
#define KK_   76       // k8 blocks (K padded to 608)
#define KPAD  608
#define ASTR  40       // A smem row stride (M=32 + 8); 40%32==8 -> conflict-free frags
#define NCHUNK 19      // 19 chunks x 4 k8-blocks

// __device__ scratch (no allocations allowed)
__device__ float g_Wcat[KTOT * H_];            // logical [k][h]
__device__ uint4 g_Bpack[KK_ * 4 * 2 * 32];    // [kk][ng][half][t] fragment-packed tf32
__device__ float g_pooled[B_ * H_];            // [b][h]

static __device__ __forceinline__ uint32_t f2tf32(float f) {
    uint32_t r; asm("cvt.rna.tf32.f32 %0, %1;" : "=r"(r) : "f"(f)); return r;
}
static __device__ __forceinline__ void mma_tf32(float c[4], const uint32_t a[4],
                                                uint32_t b0, uint32_t b1) {
    asm volatile(
        "mma.sync.aligned.m16n8k8.row.col.f32.tf32.tf32.f32 "
        "{%0,%1,%2,%3},{%4,%5,%6,%7},{%8,%9},{%0,%1,%2,%3};"
        : "+f"(c[0]), "+f"(c[1]), "+f"(c[2]), "+f"(c[3])
        : "r"(a[0]), "r"(a[1]), "r"(a[2]), "r"(a[3]), "r"(b0), "r"(b1));
}
static __device__ __forceinline__ uint64_t pk2(float lo, float hi) {
    uint64_t r; asm("mov.b64 %0, {%1, %2};" : "=l"(r) : "f"(lo), "f"(hi)); return r;
}
static __device__ __forceinline__ void upk2(uint64_t v, float& lo, float& hi) {
    asm("mov.b64 {%0, %1}, %2;" : "=f"(lo), "=f"(hi) : "l"(v));
}
static __device__ __forceinline__ uint64_t fma2(uint64_t a, uint64_t b, uint64_t c) {
    uint64_t d; asm("fma.rn.f32x2 %0, %1, %2, %3;" : "=l"(d) : "l"(a), "l"(b), "l"(c));
    return d;
}

// ---------------------------------------------------------------------------
// Kernel A: fold We/be into Wrel/Wroot/brel -> g_Wcat[585][128]
// ---------------------------------------------------------------------------
__global__ void precompute_wcat(const float* __restrict__ We,
                                const float* __restrict__ be,
                                const float* __restrict__ Wrel,
                                const float* __restrict__ Wroot,
                                const float* __restrict__ brel) {
    __shared__ float vec[H_];
    const int r = blockIdx.x;
    const int h = threadIdx.x;
    const float* Bmat;
    float addv = 0.0f;
    if (r < 512) {
        int e = r >> 6, d = r & 63;
        vec[h] = We[d * H_ + h];
        Bmat = Wrel + e * H_ * H_;
    } else if (r < 576) {
        int d = r - 512;
        vec[h] = We[d * H_ + h];
        Bmat = Wroot;
    } else if (r < 584) {
        int e = r - 576;
        vec[h] = be[h];
        Bmat = Wrel + e * H_ * H_;
    } else {
        vec[h] = be[h];
        Bmat = Wroot;
        addv = brel[h];
    }
    __syncthreads();
    float a0 = 0.f, a1 = 0.f, a2 = 0.f, a3 = 0.f;
    #pragma unroll 8
    for (int t = 0; t < H_; t += 4) {
        a0 = fmaf(vec[t],     __ldg(Bmat + (t    ) * H_ + h), a0);
        a1 = fmaf(vec[t + 1], __ldg(Bmat + (t + 1) * H_ + h), a1);
        a2 = fmaf(vec[t + 2], __ldg(Bmat + (t + 2) * H_ + h), a2);
        a3 = fmaf(vec[t + 3], __ldg(Bmat + (t + 3) * H_ + h), a3);
    }
    g_Wcat[r * H_ + h] = addv + ((a0 + a1) + (a2 + a3));
}

// ---------------------------------------------------------------------------
// Kernel A2: repack g_Wcat into mma B-fragment order (tf32), zero-pad k>=585.
// ---------------------------------------------------------------------------
__global__ void repack_b() {
    int kk   = blockIdx.x;
    int t    = threadIdx.x & 31;
    int half = (threadIdx.x >> 5) & 1;
    int ng   = threadIdx.x >> 6;
    int k0 = kk * 8 + (t & 3);
    int k1 = k0 + 4;
    int c0 = ng * 32 + (half * 2 + 0) * 8 + (t >> 2);
    int c1 = ng * 32 + (half * 2 + 1) * 8 + (t >> 2);
    float v0 = (k0 < KTOT) ? g_Wcat[k0 * H_ + c0] : 0.f;
    float v1 = (k1 < KTOT) ? g_Wcat[k1 * H_ + c0] : 0.f;
    float v2 = (k0 < KTOT) ? g_Wcat[k0 * H_ + c1] : 0.f;
    float v3 = (k1 < KTOT) ? g_Wcat[k1 * H_ + c1] : 0.f;
    g_Bpack[((kk * 4 + ng) * 2 + half) * 32 + t] =
        make_uint4(f2tf32(v0), f2tf32(v1), f2tf32(v2), f2tf32(v3));
}

// ---------------------------------------------------------------------------
// Kernel B: main kernel. ONE batch per CTA (M=32), 256 threads (8 warps),
// 99.3 KB smem -> 2 CTAs/SM: one CTA's prologue/epilogue overlaps the
// other's tensor mainloop. GEMM mainloop identical per-warp to R10
// (m32 x n64, k-split-4, B direct from L2, no barriers).
// ---------------------------------------------------------------------------
struct SmemM {
    union AB {
        float A[KPAD][ASTR];         // 97280 B, k-major: A[k][j]
        float Cpart[4][32][132];     // 67584 B: k-split partials (epilogue)
    } ab;
    unsigned masks[256];             // [e*32 + j], bit i = A[b,e,i,j]
    float    cinv[256];
};

__global__ __launch_bounds__(256, 2) void critic_main(
    const float* __restrict__ unary,    // [B,N,F]
    const int*   __restrict__ binary)   // [B,N,N,E]
{
    extern __shared__ char raw[];
    SmemM& s = *reinterpret_cast<SmemM*>(raw);

    const int tid  = threadIdx.x;
    const int lane = tid & 31;
    const int w    = tid >> 5;          // 8 warps
    const int b    = blockIdx.x;        // one batch

    // ---- u -> A root rows (pre-rounded tf32): A[512+d][j] = u[b][j][d] ----
    {
        const float* up = unary + (size_t)b * (N_ * F_);
        #pragma unroll
        for (int p = 0; p < 8; ++p) {
            int li = tid + p * 256;            // 2048 elements
            int j  = li >> 6;
            int d  = li & 63;
            s.ab.A[512 + d][j] = __uint_as_float(f2tf32(up[li]));
        }
    }
    s.masks[tid] = 0u;
    __syncthreads();

    // ---- binary -> bitmasks: thread tid has fixed (j, e-half); bit
    // i = (tid>>6) + 4p. Register-accumulate, then 4 atomicOr. ----
    {
        const int4* bb = reinterpret_cast<const int4*>(binary + (size_t)b * (N_ * N_ * E_));
        const int j  = (tid >> 1) & 31;
        const int e0 = (tid & 1) * 4;
        const int ib = tid >> 6;
        unsigned acc[4] = {0u, 0u, 0u, 0u};
        #pragma unroll
        for (int p = 0; p < 8; ++p) {
            int4 v = bb[tid + p * 256];
            unsigned bit = 1u << (ib + 4 * p);
            if (v.x) acc[0] |= bit;
            if (v.y) acc[1] |= bit;
            if (v.z) acc[2] |= bit;
            if (v.w) acc[3] |= bit;
        }
        #pragma unroll
        for (int sl = 0; sl < 4; ++sl)
            atomicOr(&s.masks[(e0 + sl) * 32 + j], acc[sl]);
    }
    __syncthreads();

    { int d = __popc(s.masks[tid]); s.cinv[tid] = d ? (1.0f / (float)d) : 0.0f; }
    __syncthreads();

    // ========================================================================
    // Tensor-core aggregation. 8 warps = (mt = w&1, np = w>>1).
    // ========================================================================
    {
        const int gr = lane >> 2, gc = lane & 3;
        const int mt = w & 1;
        const int np = w >> 1;      // 0..3

        uint32_t uf[2][4][2];       // [nt2][kb][b0/b1]
        #pragma unroll
        for (int nt2 = 0; nt2 < 2; ++nt2) {
            int nt = np * 2 + nt2;
            #pragma unroll
            for (int kb = 0; kb < 4; ++kb) {
                uf[nt2][kb][0] = __float_as_uint(s.ab.A[512 + nt * 8 + gr][kb * 8 + gc]);
                uf[nt2][kb][1] = __float_as_uint(s.ab.A[512 + nt * 8 + gr][kb * 8 + gc + 4]);
            }
        }
        const int mcol = mt * 16 + gr;
        #pragma unroll
        for (int e = 0; e < E_; ++e) {
            const int mb = e * 32 + mt * 16 + gr;
            unsigned mr0 = s.masks[mb];
            unsigned mr1 = s.masks[mb + 8];
            float ci0 = s.cinv[mb];
            float ci1 = s.cinv[mb + 8];
            float acc0[4] = {0.f, 0.f, 0.f, 0.f};
            float acc1[4] = {0.f, 0.f, 0.f, 0.f};
            #pragma unroll
            for (int kb = 0; kb < 4; ++kb) {
                int bi = kb * 8 + gc;
                uint32_t ar[4];
                ar[0] = ((mr0 >> bi) & 1u)       ? 0x3f800000u : 0u;
                ar[1] = ((mr1 >> bi) & 1u)       ? 0x3f800000u : 0u;
                ar[2] = ((mr0 >> (bi + 4)) & 1u) ? 0x3f800000u : 0u;
                ar[3] = ((mr1 >> (bi + 4)) & 1u) ? 0x3f800000u : 0u;
                mma_tf32(acc0, ar, uf[0][kb][0], uf[0][kb][1]);
                mma_tf32(acc1, ar, uf[1][kb][0], uf[1][kb][1]);
            }
            {
                int row = e * 64 + (np * 2 + 0) * 8 + 2 * gc;
                s.ab.A[row][mcol]         = __uint_as_float(f2tf32(acc0[0] * ci0));
                s.ab.A[row + 1][mcol]     = __uint_as_float(f2tf32(acc0[1] * ci0));
                s.ab.A[row][mcol + 8]     = __uint_as_float(f2tf32(acc0[2] * ci1));
                s.ab.A[row + 1][mcol + 8] = __uint_as_float(f2tf32(acc0[3] * ci1));
            }
            {
                int row = e * 64 + (np * 2 + 1) * 8 + 2 * gc;
                s.ab.A[row][mcol]         = __uint_as_float(f2tf32(acc1[0] * ci0));
                s.ab.A[row + 1][mcol]     = __uint_as_float(f2tf32(acc1[1] * ci0));
                s.ab.A[row][mcol + 8]     = __uint_as_float(f2tf32(acc1[2] * ci1));
                s.ab.A[row + 1][mcol + 8] = __uint_as_float(f2tf32(acc1[3] * ci1));
            }
        }
    }
    // special k-rows (exact in tf32): 576..583 deg>0, 584 ones, 585..607 zeros
    {
        int e2 = tid >> 5, j2 = tid & 31;
        s.ab.A[576 + e2][j2] = s.masks[tid] ? 1.0f : 0.0f;
        if (tid < 32) s.ab.A[584][tid] = 1.0f;
        for (int r = tid; r < 23 * 32; r += 256)
            s.ab.A[585 + (r >> 5)][r & 31] = 0.0f;
    }
    __syncthreads();   // A fully ready; no more barriers until epilogue

    // ========================================================================
    // Main GEMM: 8 warps = (ngp = w&1: n64 group, ks = w>>1: k8-in-chunk).
    // Warp tile m32 x n64; B direct from L2 (__ldg), depth-1 prefetch.
    // ========================================================================
    const int ngp = w & 1;
    const int ks  = w >> 1;
    const int fc  = lane & 3;
    const int fr  = lane >> 2;

    float acc[2][8][4];
    #pragma unroll
    for (int mt2 = 0; mt2 < 2; ++mt2)
        #pragma unroll
        for (int nn = 0; nn < 8; ++nn)
            #pragma unroll
            for (int i = 0; i < 4; ++i) acc[mt2][nn][i] = 0.0f;

    const uint4* bptr = g_Bpack + (size_t)((ks * 4 + ngp * 2) * 64) + lane;
    uint4 nb0 = __ldg(bptr);
    uint4 nb1 = __ldg(bptr + 32);
    uint4 nb2 = __ldg(bptr + 64);
    uint4 nb3 = __ldg(bptr + 96);

    for (int ch = 0; ch < NCHUNK; ++ch) {
        const int k0 = (ch * 4 + ks) * 8;
        uint32_t a0[4], a1[4];
        a0[0] = __float_as_uint(s.ab.A[k0 + fc][fr]);
        a0[1] = __float_as_uint(s.ab.A[k0 + fc][fr + 8]);
        a0[2] = __float_as_uint(s.ab.A[k0 + fc + 4][fr]);
        a0[3] = __float_as_uint(s.ab.A[k0 + fc + 4][fr + 8]);
        a1[0] = __float_as_uint(s.ab.A[k0 + fc][16 + fr]);
        a1[1] = __float_as_uint(s.ab.A[k0 + fc][16 + fr + 8]);
        a1[2] = __float_as_uint(s.ab.A[k0 + fc + 4][16 + fr]);
        a1[3] = __float_as_uint(s.ab.A[k0 + fc + 4][16 + fr + 8]);

        uint4 cb0 = nb0, cb1 = nb1, cb2 = nb2, cb3 = nb3;
        if (ch + 1 < NCHUNK) {
            bptr += 1024;
            nb0 = __ldg(bptr);
            nb1 = __ldg(bptr + 32);
            nb2 = __ldg(bptr + 64);
            nb3 = __ldg(bptr + 96);
        }

        mma_tf32(acc[0][0], a0, cb0.x, cb0.y);
        mma_tf32(acc[0][1], a0, cb0.z, cb0.w);
        mma_tf32(acc[0][2], a0, cb1.x, cb1.y);
        mma_tf32(acc[0][3], a0, cb1.z, cb1.w);
        mma_tf32(acc[0][4], a0, cb2.x, cb2.y);
        mma_tf32(acc[0][5], a0, cb2.z, cb2.w);
        mma_tf32(acc[0][6], a0, cb3.x, cb3.y);
        mma_tf32(acc[0][7], a0, cb3.z, cb3.w);
        mma_tf32(acc[1][0], a1, cb0.x, cb0.y);
        mma_tf32(acc[1][1], a1, cb0.z, cb0.w);
        mma_tf32(acc[1][2], a1, cb1.x, cb1.y);
        mma_tf32(acc[1][3], a1, cb1.z, cb1.w);
        mma_tf32(acc[1][4], a1, cb2.x, cb2.y);
        mma_tf32(acc[1][5], a1, cb2.z, cb2.w);
        mma_tf32(acc[1][6], a1, cb3.x, cb3.y);
        mma_tf32(acc[1][7], a1, cb3.z, cb3.w);
    }

    // ---- store k-split partials (A region dead now) ----
    __syncthreads();
    {
        float* Cp = &s.ab.Cpart[ks][0][0];
        #pragma unroll
        for (int mt2 = 0; mt2 < 2; ++mt2) {
            const int row = mt2 * 16 + fr;
            #pragma unroll
            for (int nn = 0; nn < 8; ++nn) {
                const int col = ngp * 64 + nn * 8 + 2 * fc;
                Cp[row * 132 + col]           = acc[mt2][nn][0];
                Cp[row * 132 + col + 1]       = acc[mt2][nn][1];
                Cp[(row + 8) * 132 + col]     = acc[mt2][nn][2];
                Cp[(row + 8) * 132 + col + 1] = acc[mt2][nn][3];
            }
        }
    }
    __syncthreads();

    // ---- merge partials + relu + max-pool over nodes ----
    if (tid < 128) {
        const int h = tid;
        float mx = -3.0e38f;
        #pragma unroll 4
        for (int j = 0; j < N_; ++j) {
            float v = s.ab.Cpart[0][j][h] + s.ab.Cpart[1][j][h]
                    + s.ab.Cpart[2][j][h] + s.ab.Cpart[3][j][h];
            mx = fmaxf(mx, v);
        }
        g_pooled[(size_t)b * H_ + h] = fmaxf(mx, 0.0f);
    }
}

// ---------------------------------------------------------------------------
// Kernel C: heads (passing R10 scalar version).
// ---------------------------------------------------------------------------
struct SmemH {
    float P[32][H_];
    float W[H_][H_];
    float Z[32][132];
    int   cols[32];
};

__global__ __launch_bounds__(256, 2) void heads_kernel(
    const float* __restrict__ actions,
    const float* __restrict__ W1,
    const float* __restrict__ b1,
    const float* __restrict__ W2,
    const float* __restrict__ b2,
    float* __restrict__ qout)
{
    extern __shared__ char raw[];
    SmemH& s = *reinterpret_cast<SmemH*>(raw);
    const int tid = threadIdx.x;
    const int a   = blockIdx.x >> 6;
    const int b0  = (blockIdx.x & 63) * 32;

    {
        const float4* ps = reinterpret_cast<const float4*>(g_pooled + (size_t)b0 * H_);
        float4* pd = reinterpret_cast<float4*>(&s.P[0][0]);
        #pragma unroll
        for (int p = 0; p < 4; ++p) pd[tid + p * 256] = ps[tid + p * 256];
        const float4* ws = reinterpret_cast<const float4*>(W1 + (size_t)a * H_ * H_);
        float4* wd = reinterpret_cast<float4*>(&s.W[0][0]);
        #pragma unroll
        for (int p = 0; p < 16; ++p) wd[tid + p * 256] = ws[tid + p * 256];
    }
    if (tid < 32) {
        const float* ap = actions + ((size_t)a * B_ + b0 + tid) * NACT_;
        float best = ap[0]; int col = 0;
        #pragma unroll
        for (int k = 1; k < NACT_; ++k) {
            float v = ap[k];
            if (v > best) { best = v; col = k; }
        }
        s.cols[tid] = col;
    }
    __syncthreads();
    {
        const int bi = tid >> 5;
        const int hi = tid & 31;
        float4 bv = *reinterpret_cast<const float4*>(b1 + a * H_ + hi * 4);
        uint64_t zp[4][2];
        #pragma unroll
        for (int r = 0; r < 4; ++r) {
            zp[r][0] = pk2(bv.x, bv.y);
            zp[r][1] = pk2(bv.z, bv.w);
        }
        #pragma unroll 4
        for (int k = 0; k < H_; ++k) {
            float4 wv = *reinterpret_cast<const float4*>(&s.W[k][hi * 4]);
            uint64_t w01 = pk2(wv.x, wv.y);
            uint64_t w23 = pk2(wv.z, wv.w);
            #pragma unroll
            for (int r = 0; r < 4; ++r) {
                float pv = s.P[bi * 4 + r][k];
                uint64_t pv2 = pk2(pv, pv);
                zp[r][0] = fma2(pv2, w01, zp[r][0]);
                zp[r][1] = fma2(pv2, w23, zp[r][1]);
            }
        }
        #pragma unroll
        for (int r = 0; r < 4; ++r) {
            float z0, z1, z2, z3;
            upk2(zp[r][0], z0, z1);
            upk2(zp[r][1], z2, z3);
            z0 = (z0 > 0.f) ? z0 : 0.01f * z0;
            z1 = (z1 > 0.f) ? z1 : 0.01f * z1;
            z2 = (z2 > 0.f) ? z2 : 0.01f * z2;
            z3 = (z3 > 0.f) ? z3 : 0.01f * z3;
            float* zr = &s.Z[bi * 4 + r][hi * 4];
            zr[0] = z0; zr[1] = z1; zr[2] = z2; zr[3] = z3;
        }
    }
    __syncthreads();
    {
        const int b  = tid >> 3;
        const int qt = tid & 7;
        const int col = s.cols[b];
        const float* w2p = W2 + (size_t)a * H_ * NACT_ + col;
        float part = 0.f;
        #pragma unroll 8
        for (int i = 0; i < 16; ++i) {
            int h = i * 8 + qt;
            part = fmaf(s.Z[b][h], __ldg(w2p + h * NACT_), part);
        }
        part += __shfl_xor_sync(0xffffffffu, part, 1);
        part += __shfl_xor_sync(0xffffffffu, part, 2);
        part += __shfl_xor_sync(0xffffffffu, part, 4);
        if (qt == 0)
            qout[(size_t)a * B_ + b0 + b] = part + b2[a * NACT_ + col];
    }
}

// ---------------------------------------------------------------------------
extern "C" void kernel_launch(void* const* d_in, const int* in_sizes, int n_in,
                              void* d_out, int out_size) {
    const float* unary   = (const float*)d_in[0];
    const int*   binary  = (const int*)  d_in[1];
    const float* actions = (const float*)d_in[2];
    const float* We      = (const float*)d_in[3];
    const float* be      = (const float*)d_in[4];
    const float* Wrel    = (const float*)d_in[5];
    const float* Wroot   = (const float*)d_in[6];
    const float* brel    = (const float*)d_in[7];
    const float* W1      = (const float*)d_in[8];
    const float* b1      = (const float*)d_in[9];
    const float* W2      = (const float*)d_in[10];
    const float* b2      = (const float*)d_in[11];
    float* qout = (float*)d_out;

    cudaFuncSetAttribute(critic_main, cudaFuncAttributeMaxDynamicSharedMemorySize,
                         (int)sizeof(SmemM));
    cudaFuncSetAttribute(heads_kernel, cudaFuncAttributeMaxDynamicSharedMemorySize,
                         (int)sizeof(SmemH));

    precompute_wcat<<<KTOT, H_>>>(We, be, Wrel, Wroot, brel);
    repack_b<<<KK_, 256>>>();
    critic_main<<<B_, 256, sizeof(SmemM)>>>(unary, binary);
    heads_kernel<<<NA_ * 64, 256, sizeof(SmemH)>>>(actions, W1, b1, W2, b2, qout);
}

// round 14
// speedup vs baseline: 1.5107x; 1.4563x over previous
#include <cuda_runtime.h>
#include <cuda_fp16.h>
#include <cstdint>

#define B_    2048
#define N_    32
#define F_    64
#define E_    8
#define H_    128
#define NA_   4
#define NACT_ 16
#define KTOT  585      // 512 agg + 64 root + 8 mask-bias + 1 const-bias + 1 (pad pair)
#define KK16  40       // k16 blocks (K padded to 640)
#define KP2   320      // A2 rows (fp16x2 pairs along k)
#define ASTR  40       // A2 row stride (uint32); 40%32==8 -> conflict-free frags
#define U2STR 72       // u2 row stride (uint32); 72%32==8 -> conflict-free frags
#define NCH2  20       // 20 chunks x 2 k16-blocks

// __device__ scratch (no allocations allowed)
__device__ float g_Wcat[KTOT * H_];              // logical [k][h]
__device__ uint4 g_Bpack[KK16 * 4 * 2 * 32];     // [kk16][ng][h4][t] fp16 fragment-packed
__device__ float g_pooled[B_ * H_];              // [b][h]

static __device__ __forceinline__ uint32_t pkh2(float lo, float hi) {
    __half2 h = __floats2half2_rn(lo, hi);
    return *reinterpret_cast<uint32_t*>(&h);
}
static __device__ __forceinline__ void mma_f16(float c[4], const uint32_t a[4],
                                               uint32_t b0, uint32_t b1) {
    asm volatile(
        "mma.sync.aligned.m16n8k16.row.col.f32.f16.f16.f32 "
        "{%0,%1,%2,%3},{%4,%5,%6,%7},{%8,%9},{%0,%1,%2,%3};"
        : "+f"(c[0]), "+f"(c[1]), "+f"(c[2]), "+f"(c[3])
        : "r"(a[0]), "r"(a[1]), "r"(a[2]), "r"(a[3]), "r"(b0), "r"(b1));
}
static __device__ __forceinline__ uint64_t pk2(float lo, float hi) {
    uint64_t r; asm("mov.b64 %0, {%1, %2};" : "=l"(r) : "f"(lo), "f"(hi)); return r;
}
static __device__ __forceinline__ void upk2(uint64_t v, float& lo, float& hi) {
    asm("mov.b64 {%0, %1}, %2;" : "=f"(lo), "=f"(hi) : "l"(v));
}
static __device__ __forceinline__ uint64_t fma2(uint64_t a, uint64_t b, uint64_t c) {
    uint64_t d; asm("fma.rn.f32x2 %0, %1, %2, %3;" : "=l"(d) : "l"(a), "l"(b), "l"(c));
    return d;
}

// ---------------------------------------------------------------------------
// Kernel A: fold We/be into Wrel/Wroot/brel -> g_Wcat[585][128]
// ---------------------------------------------------------------------------
__global__ void precompute_wcat(const float* __restrict__ We,
                                const float* __restrict__ be,
                                const float* __restrict__ Wrel,
                                const float* __restrict__ Wroot,
                                const float* __restrict__ brel) {
    __shared__ float vec[H_];
    const int r = blockIdx.x;
    const int h = threadIdx.x;
    const float* Bmat;
    float addv = 0.0f;
    if (r < 512) {
        int e = r >> 6, d = r & 63;
        vec[h] = We[d * H_ + h];
        Bmat = Wrel + e * H_ * H_;
    } else if (r < 576) {
        int d = r - 512;
        vec[h] = We[d * H_ + h];
        Bmat = Wroot;
    } else if (r < 584) {
        int e = r - 576;
        vec[h] = be[h];
        Bmat = Wrel + e * H_ * H_;
    } else {
        vec[h] = be[h];
        Bmat = Wroot;
        addv = brel[h];
    }
    __syncthreads();
    float a0 = 0.f, a1 = 0.f, a2 = 0.f, a3 = 0.f;
    #pragma unroll 8
    for (int t = 0; t < H_; t += 4) {
        a0 = fmaf(vec[t],     __ldg(Bmat + (t    ) * H_ + h), a0);
        a1 = fmaf(vec[t + 1], __ldg(Bmat + (t + 1) * H_ + h), a1);
        a2 = fmaf(vec[t + 2], __ldg(Bmat + (t + 2) * H_ + h), a2);
        a3 = fmaf(vec[t + 3], __ldg(Bmat + (t + 3) * H_ + h), a3);
    }
    g_Wcat[r * H_ + h] = addv + ((a0 + a1) + (a2 + a3));
}

// ---------------------------------------------------------------------------
// Kernel A2: repack g_Wcat into fp16 m16n8k16 B-fragment order, zero-pad.
// grid = 40 (kk16), block 256: t = lane, hi4 = (tid>>5)&1, ng = tid>>6.
// uint4 = {n8a.b0, n8a.b1, n8b.b0, n8b.b1}; b0 = (k0,k0+1), b1 = (k0+8,k0+9).
// ---------------------------------------------------------------------------
static __device__ __forceinline__ float wat(int k, int n) {
    return (k < KTOT) ? g_Wcat[k * H_ + n] : 0.0f;
}
__global__ void repack_b() {
    int kk  = blockIdx.x;
    int t   = threadIdx.x & 31;
    int hi4 = (threadIdx.x >> 5) & 1;
    int ng  = threadIdx.x >> 6;
    int k0  = kk * 16 + (t & 3) * 2;
    int na  = ng * 32 + (hi4 * 2 + 0) * 8 + (t >> 2);
    int nb  = ng * 32 + (hi4 * 2 + 1) * 8 + (t >> 2);
    uint4 v;
    v.x = pkh2(wat(k0, na),     wat(k0 + 1, na));
    v.y = pkh2(wat(k0 + 8, na), wat(k0 + 9, na));
    v.z = pkh2(wat(k0, nb),     wat(k0 + 1, nb));
    v.w = pkh2(wat(k0 + 8, nb), wat(k0 + 9, nb));
    g_Bpack[((kk * 4 + ng) * 2 + hi4) * 32 + t] = v;
}

// ---------------------------------------------------------------------------
// Kernel B: main kernel. ONE batch per CTA (M=32), 256 threads (8 warps),
// fp16 m16n8k16 everywhere. ~56 KB smem -> 3 CTAs/SM. Mainloop barrier-free,
// B direct from L2 with depth-1 prefetch.
// ---------------------------------------------------------------------------
struct SmemM {
    union AB {
        uint32_t A2[KP2][ASTR];      // 51200 B: fp16x2 pairs along k, [kp][j]
        float Cpart[2][32][132];     // 33792 B: k-split partials (epilogue)
    } ab;
    uint32_t u2[16][U2STR];          // 4608 B: u fp16x2 pairs along i, [ip][d]
    unsigned masks[256];             // [e*32 + j], bit i = A[b,e,i,j]
    float    cinv[256];
};

__global__ __launch_bounds__(256, 3) void critic_main(
    const float* __restrict__ unary,    // [B,N,F]
    const int*   __restrict__ binary)   // [B,N,N,E]
{
    extern __shared__ char raw[];
    SmemM& s = *reinterpret_cast<SmemM*>(raw);

    const int tid  = threadIdx.x;
    const int lane = tid & 31;
    const int w    = tid >> 5;          // 8 warps
    const int b    = blockIdx.x;        // one batch

    const float* up = unary + (size_t)b * (N_ * F_);

    // ---- u -> A2 root rows (pairs along d): A2[256+dp][j] = (u[j][2dp], u[j][2dp+1])
    {
        const float2* up2 = reinterpret_cast<const float2*>(up);
        #pragma unroll
        for (int p = 0; p < 4; ++p) {
            int idx = tid + p * 256;          // 1024 float2
            int j   = idx >> 5;
            int dp  = idx & 31;
            float2 v = up2[idx];
            s.ab.A2[256 + dp][j] = pkh2(v.x, v.y);
        }
    }
    // ---- u -> u2 (pairs along i): u2[ip][d] = (u[2ip][d], u[2ip+1][d])
    {
        #pragma unroll
        for (int p = 0; p < 4; ++p) {
            int idx = tid + p * 256;          // 1024 entries
            int ip  = idx >> 6;
            int d   = idx & 63;
            s.u2[ip][d] = pkh2(up[(2 * ip) * 64 + d], up[(2 * ip + 1) * 64 + d]);
        }
    }
    s.masks[tid] = 0u;
    __syncthreads();

    // ---- binary -> bitmasks: register-accumulate then 4 atomicOr ----
    {
        const int4* bb = reinterpret_cast<const int4*>(binary + (size_t)b * (N_ * N_ * E_));
        const int j  = (tid >> 1) & 31;
        const int e0 = (tid & 1) * 4;
        const int ib = tid >> 6;
        unsigned acc[4] = {0u, 0u, 0u, 0u};
        #pragma unroll
        for (int p = 0; p < 8; ++p) {
            int4 v = bb[tid + p * 256];
            unsigned bit = 1u << (ib + 4 * p);
            if (v.x) acc[0] |= bit;
            if (v.y) acc[1] |= bit;
            if (v.z) acc[2] |= bit;
            if (v.w) acc[3] |= bit;
        }
        #pragma unroll
        for (int sl = 0; sl < 4; ++sl)
            atomicOr(&s.masks[(e0 + sl) * 32 + j], acc[sl]);
    }
    __syncthreads();

    { int d = __popc(s.masks[tid]); s.cinv[tid] = d ? (1.0f / (float)d) : 0.0f; }
    __syncthreads();

    // ========================================================================
    // fp16 tensor-core aggregation: S_e[j][d] = sum_i adj_e[i,j] * u[i,d].
    // 8 warps = (mt = w&1: j half, np = w>>1: d-group of 16 = 2 n8 tiles).
    // Per e: 2 k16 steps x 2 n8 = 4 mma. Output packed (d, d+1) -> A2 rows.
    // ========================================================================
    {
        const int gr = lane >> 2, gc = lane & 3;
        const int mt = w & 1;
        const int np = w >> 1;      // 0..3

        uint32_t uf[2][2][2];       // [nt2][kb][b0/b1]
        #pragma unroll
        for (int nt2 = 0; nt2 < 2; ++nt2) {
            int nt = np * 2 + nt2;
            #pragma unroll
            for (int kb = 0; kb < 2; ++kb) {
                uf[nt2][kb][0] = s.u2[kb * 8 + gc][nt * 8 + gr];
                uf[nt2][kb][1] = s.u2[kb * 8 + gc + 4][nt * 8 + gr];
            }
        }
        const int mcol = mt * 16 + gr;
        #pragma unroll
        for (int e = 0; e < E_; ++e) {
            const int mb = e * 32 + mt * 16 + gr;
            unsigned mr0 = s.masks[mb];
            unsigned mr1 = s.masks[mb + 8];
            float ci0 = s.cinv[mb];
            float ci1 = s.cinv[mb + 8];
            float acc0[4] = {0.f, 0.f, 0.f, 0.f};
            float acc1[4] = {0.f, 0.f, 0.f, 0.f};
            #pragma unroll
            for (int kb = 0; kb < 2; ++kb) {
                int bi = kb * 16 + 2 * gc;
                uint32_t ar[4];
                ar[0] = (((mr0 >> bi) & 1u) ? 0x3C00u : 0u)
                      | (((mr0 >> (bi + 1)) & 1u) ? 0x3C000000u : 0u);
                ar[1] = (((mr1 >> bi) & 1u) ? 0x3C00u : 0u)
                      | (((mr1 >> (bi + 1)) & 1u) ? 0x3C000000u : 0u);
                ar[2] = (((mr0 >> (bi + 8)) & 1u) ? 0x3C00u : 0u)
                      | (((mr0 >> (bi + 9)) & 1u) ? 0x3C000000u : 0u);
                ar[3] = (((mr1 >> (bi + 8)) & 1u) ? 0x3C00u : 0u)
                      | (((mr1 >> (bi + 9)) & 1u) ? 0x3C000000u : 0u);
                mma_f16(acc0, ar, uf[0][kb][0], uf[0][kb][1]);
                mma_f16(acc1, ar, uf[1][kb][0], uf[1][kb][1]);
            }
            {
                int rp = e * 32 + (np * 2 + 0) * 4 + gc;   // (e*64 + nt*8 + 2gc)/2
                s.ab.A2[rp][mcol]     = pkh2(acc0[0] * ci0, acc0[1] * ci0);
                s.ab.A2[rp][mcol + 8] = pkh2(acc0[2] * ci1, acc0[3] * ci1);
            }
            {
                int rp = e * 32 + (np * 2 + 1) * 4 + gc;
                s.ab.A2[rp][mcol]     = pkh2(acc1[0] * ci0, acc1[1] * ci0);
                s.ab.A2[rp][mcol + 8] = pkh2(acc1[2] * ci1, acc1[3] * ci1);
            }
        }
    }
    // special rows: A rows 576..583 deg>0 pairs -> A2 288..291;
    // row 584 ones + 585 zero -> A2 292; rows 586..639 zero -> A2 293..319.
    {
        if (tid < 128) {
            int ep = tid >> 5, j2 = tid & 31;
            uint32_t v = (s.masks[(2 * ep) * 32 + j2] ? 0x3C00u : 0u)
                       | (s.masks[(2 * ep + 1) * 32 + j2] ? 0x3C000000u : 0u);
            s.ab.A2[288 + ep][j2] = v;
        }
        if (tid < 32) s.ab.A2[292][tid] = 0x3C00u;   // (1.0, 0.0)
        for (int r = tid; r < 27 * 32; r += 256)
            s.ab.A2[293 + (r >> 5)][r & 31] = 0u;
    }
    __syncthreads();   // A2 fully ready; no more barriers until epilogue

    // ========================================================================
    // Main GEMM: 8 warps = (ngp = w&3: n32 group, ks = w>>2: k16 parity).
    // Warp tile m32 x n32 x k16; 20 chunks of 2 k16; B direct from L2.
    // ========================================================================
    const int ngp = w & 3;
    const int ks  = w >> 2;
    const int fc  = lane & 3;
    const int fr  = lane >> 2;

    float acc[2][4][4];
    #pragma unroll
    for (int mt2 = 0; mt2 < 2; ++mt2)
        #pragma unroll
        for (int nn = 0; nn < 4; ++nn)
            #pragma unroll
            for (int i = 0; i < 4; ++i) acc[mt2][nn][i] = 0.0f;

    const uint4* bptr = g_Bpack + (size_t)(((ks * 4 + ngp) * 2) * 32) + lane;
    uint4 nb0 = __ldg(bptr);
    uint4 nb1 = __ldg(bptr + 32);

    for (int ch = 0; ch < NCH2; ++ch) {
        const int kp0 = (ch * 2 + ks) * 8;
        uint32_t a0[4], a1[4];
        a0[0] = s.ab.A2[kp0 + fc][fr];
        a0[1] = s.ab.A2[kp0 + fc][fr + 8];
        a0[2] = s.ab.A2[kp0 + fc + 4][fr];
        a0[3] = s.ab.A2[kp0 + fc + 4][fr + 8];
        a1[0] = s.ab.A2[kp0 + fc][16 + fr];
        a1[1] = s.ab.A2[kp0 + fc][16 + fr + 8];
        a1[2] = s.ab.A2[kp0 + fc + 4][16 + fr];
        a1[3] = s.ab.A2[kp0 + fc + 4][16 + fr + 8];

        uint4 cb0 = nb0, cb1 = nb1;
        if (ch + 1 < NCH2) {
            bptr += 512;               // 2 k16 * 4 ng * 2 * 32
            nb0 = __ldg(bptr);
            nb1 = __ldg(bptr + 32);
        }

        mma_f16(acc[0][0], a0, cb0.x, cb0.y);
        mma_f16(acc[0][1], a0, cb0.z, cb0.w);
        mma_f16(acc[0][2], a0, cb1.x, cb1.y);
        mma_f16(acc[0][3], a0, cb1.z, cb1.w);
        mma_f16(acc[1][0], a1, cb0.x, cb0.y);
        mma_f16(acc[1][1], a1, cb0.z, cb0.w);
        mma_f16(acc[1][2], a1, cb1.x, cb1.y);
        mma_f16(acc[1][3], a1, cb1.z, cb1.w);
    }

    // ---- store k-split partials (A2 region dead now) ----
    __syncthreads();
    {
        float* Cp = &s.ab.Cpart[ks][0][0];
        #pragma unroll
        for (int mt2 = 0; mt2 < 2; ++mt2) {
            const int row = mt2 * 16 + fr;
            #pragma unroll
            for (int nn = 0; nn < 4; ++nn) {
                const int col = ngp * 32 + nn * 8 + 2 * fc;
                Cp[row * 132 + col]           = acc[mt2][nn][0];
                Cp[row * 132 + col + 1]       = acc[mt2][nn][1];
                Cp[(row + 8) * 132 + col]     = acc[mt2][nn][2];
                Cp[(row + 8) * 132 + col + 1] = acc[mt2][nn][3];
            }
        }
    }
    __syncthreads();

    // ---- merge partials + relu + max-pool over nodes ----
    if (tid < 128) {
        const int h = tid;
        float mx = -3.0e38f;
        #pragma unroll 4
        for (int j = 0; j < N_; ++j) {
            float v = s.ab.Cpart[0][j][h] + s.ab.Cpart[1][j][h];
            mx = fmaxf(mx, v);
        }
        g_pooled[(size_t)b * H_ + h] = fmaxf(mx, 0.0f);
    }
}

// ---------------------------------------------------------------------------
// Kernel C: heads (passing R10 scalar version).
// ---------------------------------------------------------------------------
struct SmemH {
    float P[32][H_];
    float W[H_][H_];
    float Z[32][132];
    int   cols[32];
};

__global__ __launch_bounds__(256, 2) void heads_kernel(
    const float* __restrict__ actions,
    const float* __restrict__ W1,
    const float* __restrict__ b1,
    const float* __restrict__ W2,
    const float* __restrict__ b2,
    float* __restrict__ qout)
{
    extern __shared__ char raw[];
    SmemH& s = *reinterpret_cast<SmemH*>(raw);
    const int tid = threadIdx.x;
    const int a   = blockIdx.x >> 6;
    const int b0  = (blockIdx.x & 63) * 32;

    {
        const float4* ps = reinterpret_cast<const float4*>(g_pooled + (size_t)b0 * H_);
        float4* pd = reinterpret_cast<float4*>(&s.P[0][0]);
        #pragma unroll
        for (int p = 0; p < 4; ++p) pd[tid + p * 256] = ps[tid + p * 256];
        const float4* ws = reinterpret_cast<const float4*>(W1 + (size_t)a * H_ * H_);
        float4* wd = reinterpret_cast<float4*>(&s.W[0][0]);
        #pragma unroll
        for (int p = 0; p < 16; ++p) wd[tid + p * 256] = ws[tid + p * 256];
    }
    if (tid < 32) {
        const float* ap = actions + ((size_t)a * B_ + b0 + tid) * NACT_;
        float best = ap[0]; int col = 0;
        #pragma unroll
        for (int k = 1; k < NACT_; ++k) {
            float v = ap[k];
            if (v > best) { best = v; col = k; }
        }
        s.cols[tid] = col;
    }
    __syncthreads();
    {
        const int bi = tid >> 5;
        const int hi = tid & 31;
        float4 bv = *reinterpret_cast<const float4*>(b1 + a * H_ + hi * 4);
        uint64_t zp[4][2];
        #pragma unroll
        for (int r = 0; r < 4; ++r) {
            zp[r][0] = pk2(bv.x, bv.y);
            zp[r][1] = pk2(bv.z, bv.w);
        }
        #pragma unroll 4
        for (int k = 0; k < H_; ++k) {
            float4 wv = *reinterpret_cast<const float4*>(&s.W[k][hi * 4]);
            uint64_t w01 = pk2(wv.x, wv.y);
            uint64_t w23 = pk2(wv.z, wv.w);
            #pragma unroll
            for (int r = 0; r < 4; ++r) {
                float pv = s.P[bi * 4 + r][k];
                uint64_t pv2 = pk2(pv, pv);
                zp[r][0] = fma2(pv2, w01, zp[r][0]);
                zp[r][1] = fma2(pv2, w23, zp[r][1]);
            }
        }
        #pragma unroll
        for (int r = 0; r < 4; ++r) {
            float z0, z1, z2, z3;
            upk2(zp[r][0], z0, z1);
            upk2(zp[r][1], z2, z3);
            z0 = (z0 > 0.f) ? z0 : 0.01f * z0;
            z1 = (z1 > 0.f) ? z1 : 0.01f * z1;
            z2 = (z2 > 0.f) ? z2 : 0.01f * z2;
            z3 = (z3 > 0.f) ? z3 : 0.01f * z3;
            float* zr = &s.Z[bi * 4 + r][hi * 4];
            zr[0] = z0; zr[1] = z1; zr[2] = z2; zr[3] = z3;
        }
    }
    __syncthreads();
    {
        const int b  = tid >> 3;
        const int qt = tid & 7;
        const int col = s.cols[b];
        const float* w2p = W2 + (size_t)a * H_ * NACT_ + col;
        float part = 0.f;
        #pragma unroll 8
        for (int i = 0; i < 16; ++i) {
            int h = i * 8 + qt;
            part = fmaf(s.Z[b][h], __ldg(w2p + h * NACT_), part);
        }
        part += __shfl_xor_sync(0xffffffffu, part, 1);
        part += __shfl_xor_sync(0xffffffffu, part, 2);
        part += __shfl_xor_sync(0xffffffffu, part, 4);
        if (qt == 0)
            qout[(size_t)a * B_ + b0 + b] = part + b2[a * NACT_ + col];
    }
}

// ---------------------------------------------------------------------------
extern "C" void kernel_launch(void* const* d_in, const int* in_sizes, int n_in,
                              void* d_out, int out_size) {
    const float* unary   = (const float*)d_in[0];
    const int*   binary  = (const int*)  d_in[1];
    const float* actions = (const float*)d_in[2];
    const float* We      = (const float*)d_in[3];
    const float* be      = (const float*)d_in[4];
    const float* Wrel    = (const float*)d_in[5];
    const float* Wroot   = (const float*)d_in[6];
    const float* brel    = (const float*)d_in[7];
    const float* W1      = (const float*)d_in[8];
    const float* b1      = (const float*)d_in[9];
    const float* W2      = (const float*)d_in[10];
    const float* b2      = (const float*)d_in[11];
    float* qout = (float*)d_out;

    cudaFuncSetAttribute(critic_main, cudaFuncAttributeMaxDynamicSharedMemorySize,
                         (int)sizeof(SmemM));
    cudaFuncSetAttribute(heads_kernel, cudaFuncAttributeMaxDynamicSharedMemorySize,
                         (int)sizeof(SmemH));

    precompute_wcat<<<KTOT, H_>>>(We, be, Wrel, Wroot, brel);
    repack_b<<<KK16, 256>>>();
    critic_main<<<B_, 256, sizeof(SmemM)>>>(unary, binary);
    heads_kernel<<<NA_ * 64, 256, sizeof(SmemH)>>>(actions, W1, b1, W2, b2, qout);
}

// round 16
// speedup vs baseline: 1.6673x; 1.1036x over previous
#include <cuda_runtime.h>
#include <cuda_fp16.h>
#include <cstdint>

#define B_    2048
#define N_    32
#define F_    64
#define E_    8
#define H_    128
#define NA_   4
#define NACT_ 16
#define KTOT  585      // 512 agg + 64 root + 8 mask-bias + 1 const-bias + 1 (pad pair)
#define KK16  40       // k16 blocks (K padded to 640)
#define KP2   320      // A2 rows (fp16x2 pairs along k)
#define ASTR  40       // A2 row stride (uint32); 40%32==8 -> conflict-free frags
#define HSTR  72       // heads Ah row stride (uint32); 72%32==8 -> conflict-free
#define U2STR 72       // u2 row stride (uint32); 72%32==8 -> conflict-free frags
#define NCH2  20       // 20 chunks x 2 k16-blocks

// __device__ scratch (no allocations allowed)
__device__ float g_Wcat[KTOT * H_];              // logical [k][h]
__device__ uint4 g_Bpack[KK16 * 4 * 2 * 32];     // [kk16][ng][h4][t] fp16 fragment-packed
__device__ uint4 g_W1pack[NA_ * 8 * 4 * 2 * 32]; // [a][kk16][ng][h4][t] fp16 fragments
__device__ float g_pooled[B_ * H_];              // [b][h]

static __device__ __forceinline__ uint32_t pkh2(float lo, float hi) {
    __half2 h = __floats2half2_rn(lo, hi);
    return *reinterpret_cast<uint32_t*>(&h);
}
static __device__ __forceinline__ void mma_f16(float c[4], const uint32_t a[4],
                                               uint32_t b0, uint32_t b1) {
    asm volatile(
        "mma.sync.aligned.m16n8k16.row.col.f32.f16.f16.f32 "
        "{%0,%1,%2,%3},{%4,%5,%6,%7},{%8,%9},{%0,%1,%2,%3};"
        : "+f"(c[0]), "+f"(c[1]), "+f"(c[2]), "+f"(c[3])
        : "r"(a[0]), "r"(a[1]), "r"(a[2]), "r"(a[3]), "r"(b0), "r"(b1));
}

// ---------------------------------------------------------------------------
// Kernel A: fold We/be into Wrel/Wroot/brel -> g_Wcat[585][128]
// ---------------------------------------------------------------------------
__global__ void precompute_wcat(const float* __restrict__ We,
                                const float* __restrict__ be,
                                const float* __restrict__ Wrel,
                                const float* __restrict__ Wroot,
                                const float* __restrict__ brel) {
    __shared__ float vec[H_];
    const int r = blockIdx.x;
    const int h = threadIdx.x;
    const float* Bmat;
    float addv = 0.0f;
    if (r < 512) {
        int e = r >> 6, d = r & 63;
        vec[h] = We[d * H_ + h];
        Bmat = Wrel + e * H_ * H_;
    } else if (r < 576) {
        int d = r - 512;
        vec[h] = We[d * H_ + h];
        Bmat = Wroot;
    } else if (r < 584) {
        int e = r - 576;
        vec[h] = be[h];
        Bmat = Wrel + e * H_ * H_;
    } else {
        vec[h] = be[h];
        Bmat = Wroot;
        addv = brel[h];
    }
    __syncthreads();
    float a0 = 0.f, a1 = 0.f, a2 = 0.f, a3 = 0.f;
    #pragma unroll 8
    for (int t = 0; t < H_; t += 4) {
        a0 = fmaf(vec[t],     __ldg(Bmat + (t    ) * H_ + h), a0);
        a1 = fmaf(vec[t + 1], __ldg(Bmat + (t + 1) * H_ + h), a1);
        a2 = fmaf(vec[t + 2], __ldg(Bmat + (t + 2) * H_ + h), a2);
        a3 = fmaf(vec[t + 3], __ldg(Bmat + (t + 3) * H_ + h), a3);
    }
    g_Wcat[r * H_ + h] = addv + ((a0 + a1) + (a2 + a3));
}

// ---------------------------------------------------------------------------
// Kernel A2: pack fragments. Blocks 0..39: g_Wcat -> g_Bpack (zero-pad k>=585).
// Blocks 40..71: W1 -> g_W1pack (a = (bx-40)>>3, kk = (bx-40)&7, K=128 exact).
// ---------------------------------------------------------------------------
static __device__ __forceinline__ float wat(int k, int n) {
    return (k < KTOT) ? g_Wcat[k * H_ + n] : 0.0f;
}
__global__ void repack_b(const float* __restrict__ W1) {
    int t   = threadIdx.x & 31;
    int hi4 = (threadIdx.x >> 5) & 1;
    int ng  = threadIdx.x >> 6;
    if (blockIdx.x < KK16) {
        int kk  = blockIdx.x;
        int k0  = kk * 16 + (t & 3) * 2;
        int na  = ng * 32 + (hi4 * 2 + 0) * 8 + (t >> 2);
        int nb  = ng * 32 + (hi4 * 2 + 1) * 8 + (t >> 2);
        uint4 v;
        v.x = pkh2(wat(k0, na),     wat(k0 + 1, na));
        v.y = pkh2(wat(k0 + 8, na), wat(k0 + 9, na));
        v.z = pkh2(wat(k0, nb),     wat(k0 + 1, nb));
        v.w = pkh2(wat(k0 + 8, nb), wat(k0 + 9, nb));
        g_Bpack[((kk * 4 + ng) * 2 + hi4) * 32 + t] = v;
    } else {
        int a   = (blockIdx.x - KK16) >> 3;
        int kk  = (blockIdx.x - KK16) & 7;
        int k0  = kk * 16 + (t & 3) * 2;
        int na  = ng * 32 + (hi4 * 2 + 0) * 8 + (t >> 2);
        int nb  = ng * 32 + (hi4 * 2 + 1) * 8 + (t >> 2);
        const float* Wp = W1 + (size_t)a * H_ * H_;
        uint4 v;
        v.x = pkh2(Wp[k0 * H_ + na],       Wp[(k0 + 1) * H_ + na]);
        v.y = pkh2(Wp[(k0 + 8) * H_ + na], Wp[(k0 + 9) * H_ + na]);
        v.z = pkh2(Wp[k0 * H_ + nb],       Wp[(k0 + 1) * H_ + nb]);
        v.w = pkh2(Wp[(k0 + 8) * H_ + nb], Wp[(k0 + 9) * H_ + nb]);
        g_W1pack[(((a * 8 + kk) * 4 + ng) * 2 + hi4) * 32 + t] = v;
    }
}

// ---------------------------------------------------------------------------
// Kernel B: main kernel (byte-identical to passing R14 version).
// ---------------------------------------------------------------------------
struct SmemM {
    union AB {
        uint32_t A2[KP2][ASTR];      // 51200 B: fp16x2 pairs along k, [kp][j]
        float Cpart[2][32][132];     // 33792 B: k-split partials (epilogue)
    } ab;
    uint32_t u2[16][U2STR];          // 4608 B: u fp16x2 pairs along i, [ip][d]
    unsigned masks[256];             // [e*32 + j], bit i = A[b,e,i,j]
    float    cinv[256];
};

__global__ __launch_bounds__(256, 3) void critic_main(
    const float* __restrict__ unary,    // [B,N,F]
    const int*   __restrict__ binary)   // [B,N,N,E]
{
    extern __shared__ char raw[];
    SmemM& s = *reinterpret_cast<SmemM*>(raw);

    const int tid  = threadIdx.x;
    const int lane = tid & 31;
    const int w    = tid >> 5;          // 8 warps
    const int b    = blockIdx.x;        // one batch

    const float* up = unary + (size_t)b * (N_ * F_);

    // ---- u -> A2 root rows (pairs along d): A2[256+dp][j] = (u[j][2dp], u[j][2dp+1])
    {
        const float2* up2 = reinterpret_cast<const float2*>(up);
        #pragma unroll
        for (int p = 0; p < 4; ++p) {
            int idx = tid + p * 256;          // 1024 float2
            int j   = idx >> 5;
            int dp  = idx & 31;
            float2 v = up2[idx];
            s.ab.A2[256 + dp][j] = pkh2(v.x, v.y);
        }
    }
    // ---- u -> u2 (pairs along i): u2[ip][d] = (u[2ip][d], u[2ip+1][d])
    {
        #pragma unroll
        for (int p = 0; p < 4; ++p) {
            int idx = tid + p * 256;          // 1024 entries
            int ip  = idx >> 6;
            int d   = idx & 63;
            s.u2[ip][d] = pkh2(up[(2 * ip) * 64 + d], up[(2 * ip + 1) * 64 + d]);
        }
    }
    s.masks[tid] = 0u;
    __syncthreads();

    // ---- binary -> bitmasks: register-accumulate then 4 atomicOr ----
    {
        const int4* bb = reinterpret_cast<const int4*>(binary + (size_t)b * (N_ * N_ * E_));
        const int j  = (tid >> 1) & 31;
        const int e0 = (tid & 1) * 4;
        const int ib = tid >> 6;
        unsigned acc[4] = {0u, 0u, 0u, 0u};
        #pragma unroll
        for (int p = 0; p < 8; ++p) {
            int4 v = bb[tid + p * 256];
            unsigned bit = 1u << (ib + 4 * p);
            if (v.x) acc[0] |= bit;
            if (v.y) acc[1] |= bit;
            if (v.z) acc[2] |= bit;
            if (v.w) acc[3] |= bit;
        }
        #pragma unroll
        for (int sl = 0; sl < 4; ++sl)
            atomicOr(&s.masks[(e0 + sl) * 32 + j], acc[sl]);
    }
    __syncthreads();

    { int d = __popc(s.masks[tid]); s.cinv[tid] = d ? (1.0f / (float)d) : 0.0f; }
    __syncthreads();

    // ========================================================================
    // fp16 tensor-core aggregation: S_e[j][d] = sum_i adj_e[i,j] * u[i,d].
    // ========================================================================
    {
        const int gr = lane >> 2, gc = lane & 3;
        const int mt = w & 1;
        const int np = w >> 1;      // 0..3

        uint32_t uf[2][2][2];       // [nt2][kb][b0/b1]
        #pragma unroll
        for (int nt2 = 0; nt2 < 2; ++nt2) {
            int nt = np * 2 + nt2;
            #pragma unroll
            for (int kb = 0; kb < 2; ++kb) {
                uf[nt2][kb][0] = s.u2[kb * 8 + gc][nt * 8 + gr];
                uf[nt2][kb][1] = s.u2[kb * 8 + gc + 4][nt * 8 + gr];
            }
        }
        const int mcol = mt * 16 + gr;
        #pragma unroll
        for (int e = 0; e < E_; ++e) {
            const int mb = e * 32 + mt * 16 + gr;
            unsigned mr0 = s.masks[mb];
            unsigned mr1 = s.masks[mb + 8];
            float ci0 = s.cinv[mb];
            float ci1 = s.cinv[mb + 8];
            float acc0[4] = {0.f, 0.f, 0.f, 0.f};
            float acc1[4] = {0.f, 0.f, 0.f, 0.f};
            #pragma unroll
            for (int kb = 0; kb < 2; ++kb) {
                int bi = kb * 16 + 2 * gc;
                uint32_t ar[4];
                ar[0] = (((mr0 >> bi) & 1u) ? 0x3C00u : 0u)
                      | (((mr0 >> (bi + 1)) & 1u) ? 0x3C000000u : 0u);
                ar[1] = (((mr1 >> bi) & 1u) ? 0x3C00u : 0u)
                      | (((mr1 >> (bi + 1)) & 1u) ? 0x3C000000u : 0u);
                ar[2] = (((mr0 >> (bi + 8)) & 1u) ? 0x3C00u : 0u)
                      | (((mr0 >> (bi + 9)) & 1u) ? 0x3C000000u : 0u);
                ar[3] = (((mr1 >> (bi + 8)) & 1u) ? 0x3C00u : 0u)
                      | (((mr1 >> (bi + 9)) & 1u) ? 0x3C000000u : 0u);
                mma_f16(acc0, ar, uf[0][kb][0], uf[0][kb][1]);
                mma_f16(acc1, ar, uf[1][kb][0], uf[1][kb][1]);
            }
            {
                int rp = e * 32 + (np * 2 + 0) * 4 + gc;
                s.ab.A2[rp][mcol]     = pkh2(acc0[0] * ci0, acc0[1] * ci0);
                s.ab.A2[rp][mcol + 8] = pkh2(acc0[2] * ci1, acc0[3] * ci1);
            }
            {
                int rp = e * 32 + (np * 2 + 1) * 4 + gc;
                s.ab.A2[rp][mcol]     = pkh2(acc1[0] * ci0, acc1[1] * ci0);
                s.ab.A2[rp][mcol + 8] = pkh2(acc1[2] * ci1, acc1[3] * ci1);
            }
        }
    }
    // special rows: A rows 576..583 deg>0 pairs -> A2 288..291;
    // row 584 ones + 585 zero -> A2 292; rows 586..639 zero -> A2 293..319.
    {
        if (tid < 128) {
            int ep = tid >> 5, j2 = tid & 31;
            uint32_t v = (s.masks[(2 * ep) * 32 + j2] ? 0x3C00u : 0u)
                       | (s.masks[(2 * ep + 1) * 32 + j2] ? 0x3C000000u : 0u);
            s.ab.A2[288 + ep][j2] = v;
        }
        if (tid < 32) s.ab.A2[292][tid] = 0x3C00u;   // (1.0, 0.0)
        for (int r = tid; r < 27 * 32; r += 256)
            s.ab.A2[293 + (r >> 5)][r & 31] = 0u;
    }
    __syncthreads();   // A2 fully ready; no more barriers until epilogue

    // ========================================================================
    // Main GEMM: 8 warps = (ngp = w&3: n32 group, ks = w>>2: k16 parity).
    // ========================================================================
    const int ngp = w & 3;
    const int ks  = w >> 2;
    const int fc  = lane & 3;
    const int fr  = lane >> 2;

    float acc[2][4][4];
    #pragma unroll
    for (int mt2 = 0; mt2 < 2; ++mt2)
        #pragma unroll
        for (int nn = 0; nn < 4; ++nn)
            #pragma unroll
            for (int i = 0; i < 4; ++i) acc[mt2][nn][i] = 0.0f;

    const uint4* bptr = g_Bpack + (size_t)(((ks * 4 + ngp) * 2) * 32) + lane;
    uint4 nb0 = __ldg(bptr);
    uint4 nb1 = __ldg(bptr + 32);

    for (int ch = 0; ch < NCH2; ++ch) {
        const int kp0 = (ch * 2 + ks) * 8;
        uint32_t a0[4], a1[4];
        a0[0] = s.ab.A2[kp0 + fc][fr];
        a0[1] = s.ab.A2[kp0 + fc][fr + 8];
        a0[2] = s.ab.A2[kp0 + fc + 4][fr];
        a0[3] = s.ab.A2[kp0 + fc + 4][fr + 8];
        a1[0] = s.ab.A2[kp0 + fc][16 + fr];
        a1[1] = s.ab.A2[kp0 + fc][16 + fr + 8];
        a1[2] = s.ab.A2[kp0 + fc + 4][16 + fr];
        a1[3] = s.ab.A2[kp0 + fc + 4][16 + fr + 8];

        uint4 cb0 = nb0, cb1 = nb1;
        if (ch + 1 < NCH2) {
            bptr += 512;
            nb0 = __ldg(bptr);
            nb1 = __ldg(bptr + 32);
        }

        mma_f16(acc[0][0], a0, cb0.x, cb0.y);
        mma_f16(acc[0][1], a0, cb0.z, cb0.w);
        mma_f16(acc[0][2], a0, cb1.x, cb1.y);
        mma_f16(acc[0][3], a0, cb1.z, cb1.w);
        mma_f16(acc[1][0], a1, cb0.x, cb0.y);
        mma_f16(acc[1][1], a1, cb0.z, cb0.w);
        mma_f16(acc[1][2], a1, cb1.x, cb1.y);
        mma_f16(acc[1][3], a1, cb1.z, cb1.w);
    }

    // ---- store k-split partials (A2 region dead now) ----
    __syncthreads();
    {
        float* Cp = &s.ab.Cpart[ks][0][0];
        #pragma unroll
        for (int mt2 = 0; mt2 < 2; ++mt2) {
            const int row = mt2 * 16 + fr;
            #pragma unroll
            for (int nn = 0; nn < 4; ++nn) {
                const int col = ngp * 32 + nn * 8 + 2 * fc;
                Cp[row * 132 + col]           = acc[mt2][nn][0];
                Cp[row * 132 + col + 1]       = acc[mt2][nn][1];
                Cp[(row + 8) * 132 + col]     = acc[mt2][nn][2];
                Cp[(row + 8) * 132 + col + 1] = acc[mt2][nn][3];
            }
        }
    }
    __syncthreads();

    // ---- merge partials + relu + max-pool over nodes ----
    if (tid < 128) {
        const int h = tid;
        float mx = -3.0e38f;
        #pragma unroll 4
        for (int j = 0; j < N_; ++j) {
            float v = s.ab.Cpart[0][j][h] + s.ab.Cpart[1][j][h];
            mx = fmaxf(mx, v);
        }
        g_pooled[(size_t)b * H_ + h] = fmaxf(mx, 0.0f);
    }
}

// ---------------------------------------------------------------------------
// Kernel C: heads via fp16 mma. grid = 4 agents x 32 tiles of 64 batches
// (128 CTAs), 256 threads (8 warps = 2 m32-tiles x 4 n32-groups). K=128 = 8
// k16 steps, W1 fragments direct from L2 with depth-1 prefetch. Ah stride 72
// (m = 64 batches + 8 pad) -- fixes the R15 out-of-bounds bug.
// ---------------------------------------------------------------------------
struct SmemH {
    union AZ {
        uint32_t Ah[64][HSTR];    // 18432 B: pooled fp16x2 pairs, [kp][m], m<64
        float Z[64][132];         // 33792 B: z (epilogue)
    } az;
    int cols[64];
};

__global__ __launch_bounds__(256, 2) void heads_kernel(
    const float* __restrict__ actions,  // [NA,B,NACT]
    const float* __restrict__ b1,       // [NA,H]
    const float* __restrict__ W2,       // [NA,H,NACT]
    const float* __restrict__ b2,       // [NA,NACT]
    float* __restrict__ qout)           // [NA,B,1]
{
    extern __shared__ char raw[];
    SmemH& s = *reinterpret_cast<SmemH*>(raw);
    const int tid  = threadIdx.x;
    const int lane = tid & 31;
    const int w    = tid >> 5;
    const int a    = blockIdx.x >> 5;
    const int b0   = (blockIdx.x & 31) * 64;

    // ---- stage pooled transposed as fp16x2 pairs: Ah[hp][m] ----
    {
        const float2* ps = reinterpret_cast<const float2*>(g_pooled + (size_t)b0 * H_);
        #pragma unroll
        for (int p = 0; p < 16; ++p) {
            int idx = tid + p * 256;          // 4096 float2
            int m   = idx >> 6;               // batch 0..63
            int hp  = idx & 63;               // h pair 0..63
            float2 v = ps[idx];
            s.az.Ah[hp][m] = pkh2(v.x, v.y);
        }
    }
    if (tid < 64) {
        const float* ap = actions + ((size_t)a * B_ + b0 + tid) * NACT_;
        float best = ap[0]; int col = 0;
        #pragma unroll
        for (int k = 1; k < NACT_; ++k) {
            float v = ap[k];
            if (v > best) { best = v; col = k; }
        }
        s.cols[tid] = col;
    }
    __syncthreads();

    // ---- z GEMM: warp = (mw2 = w&1: m32 tile, ng = w>>1: n32 group) ----
    const int mw2 = w & 1;
    const int ng  = w >> 1;
    const int fc  = lane & 3;
    const int fr  = lane >> 2;
    const int m0  = mw2 * 32;

    float acc[2][4][4];
    #pragma unroll
    for (int mt2 = 0; mt2 < 2; ++mt2)
        #pragma unroll
        for (int nn = 0; nn < 4; ++nn)
            #pragma unroll
            for (int i = 0; i < 4; ++i) acc[mt2][nn][i] = 0.0f;

    const uint4* bptr = g_W1pack + (size_t)(((a * 8) * 4 + ng) * 2) * 32 + lane;
    uint4 nb0 = __ldg(bptr);
    uint4 nb1 = __ldg(bptr + 32);

    #pragma unroll
    for (int kk = 0; kk < 8; ++kk) {
        const int kp0 = kk * 8;
        uint32_t a0[4], a1[4];
        a0[0] = s.az.Ah[kp0 + fc][m0 + fr];
        a0[1] = s.az.Ah[kp0 + fc][m0 + fr + 8];
        a0[2] = s.az.Ah[kp0 + fc + 4][m0 + fr];
        a0[3] = s.az.Ah[kp0 + fc + 4][m0 + fr + 8];
        a1[0] = s.az.Ah[kp0 + fc][m0 + 16 + fr];
        a1[1] = s.az.Ah[kp0 + fc][m0 + 16 + fr + 8];
        a1[2] = s.az.Ah[kp0 + fc + 4][m0 + 16 + fr];
        a1[3] = s.az.Ah[kp0 + fc + 4][m0 + 16 + fr + 8];

        uint4 cb0 = nb0, cb1 = nb1;
        if (kk + 1 < 8) {
            bptr += 256;                // 4 ng * 2 * 32
            nb0 = __ldg(bptr);
            nb1 = __ldg(bptr + 32);
        }

        mma_f16(acc[0][0], a0, cb0.x, cb0.y);
        mma_f16(acc[0][1], a0, cb0.z, cb0.w);
        mma_f16(acc[0][2], a0, cb1.x, cb1.y);
        mma_f16(acc[0][3], a0, cb1.z, cb1.w);
        mma_f16(acc[1][0], a1, cb0.x, cb0.y);
        mma_f16(acc[1][1], a1, cb0.z, cb0.w);
        mma_f16(acc[1][2], a1, cb1.x, cb1.y);
        mma_f16(acc[1][3], a1, cb1.z, cb1.w);
    }
    __syncthreads();   // all warps done reading Ah; Z overlays it

    // ---- epilogue: +b1, LeakyReLU, store Z ----
    #pragma unroll
    for (int nn = 0; nn < 4; ++nn) {
        const int col = ng * 32 + nn * 8 + 2 * fc;
        float bv0 = __ldg(b1 + a * H_ + col);
        float bv1 = __ldg(b1 + a * H_ + col + 1);
        #pragma unroll
        for (int mt2 = 0; mt2 < 2; ++mt2) {
            const int row = m0 + mt2 * 16 + fr;
            float z00 = acc[mt2][nn][0] + bv0;
            float z01 = acc[mt2][nn][1] + bv1;
            float z10 = acc[mt2][nn][2] + bv0;
            float z11 = acc[mt2][nn][3] + bv1;
            s.az.Z[row][col]         = (z00 > 0.f) ? z00 : 0.01f * z00;
            s.az.Z[row][col + 1]     = (z01 > 0.f) ? z01 : 0.01f * z01;
            s.az.Z[row + 8][col]     = (z10 > 0.f) ? z10 : 0.01f * z10;
            s.az.Z[row + 8][col + 1] = (z11 > 0.f) ? z11 : 0.01f * z11;
        }
    }
    __syncthreads();

    // ---- q = z @ W2[:, col] + b2: thread = (b = tid>>2, qt = tid&3), 32 h ----
    {
        const int b  = tid >> 2;
        const int qt = tid & 3;
        const int col = s.cols[b];
        const float* w2p = W2 + (size_t)a * H_ * NACT_ + col;
        float part = 0.f;
        #pragma unroll 8
        for (int i = 0; i < 32; ++i) {
            int h = i * 4 + qt;
            part = fmaf(s.az.Z[b][h], __ldg(w2p + h * NACT_), part);
        }
        part += __shfl_xor_sync(0xffffffffu, part, 1);
        part += __shfl_xor_sync(0xffffffffu, part, 2);
        if (qt == 0)
            qout[(size_t)a * B_ + b0 + b] = part + b2[a * NACT_ + col];
    }
}

// ---------------------------------------------------------------------------
extern "C" void kernel_launch(void* const* d_in, const int* in_sizes, int n_in,
                              void* d_out, int out_size) {
    const float* unary   = (const float*)d_in[0];
    const int*   binary  = (const int*)  d_in[1];
    const float* actions = (const float*)d_in[2];
    const float* We      = (const float*)d_in[3];
    const float* be      = (const float*)d_in[4];
    const float* Wrel    = (const float*)d_in[5];
    const float* Wroot   = (const float*)d_in[6];
    const float* brel    = (const float*)d_in[7];
    const float* W1      = (const float*)d_in[8];
    const float* b1      = (const float*)d_in[9];
    const float* W2      = (const float*)d_in[10];
    const float* b2      = (const float*)d_in[11];
    float* qout = (float*)d_out;

    cudaFuncSetAttribute(critic_main, cudaFuncAttributeMaxDynamicSharedMemorySize,
                         (int)sizeof(SmemM));
    cudaFuncSetAttribute(heads_kernel, cudaFuncAttributeMaxDynamicSharedMemorySize,
                         (int)sizeof(SmemH));

    precompute_wcat<<<KTOT, H_>>>(We, be, Wrel, Wroot, brel);
    repack_b<<<KK16 + NA_ * 8, 256>>>(W1);
    critic_main<<<B_, 256, sizeof(SmemM)>>>(unary, binary);
    heads_kernel<<<NA_ * 32, 256, sizeof(SmemH)>>>(actions, b1, W2, b2, qout);
}